// round 14
// baseline (speedup 1.0000x reference)
#include <cuda_runtime.h>
#include <math.h>
#include <stdint.h>

#define Bb 16
#define Nn 200
#define Dd 128
#define Hh 8
#define ROWS (Bb*Nn)          // 3200
#define NEG_SLOPE 0.2f
#define RPB 16                // rows per gemm block
#define HS 20                 // hT row stride (floats)
#define ES9 9                 // esh2 row stride (conflict-free softmax)
#define NGEMM 208             // producer blocks (200 gemm + 8 c3)

// Scratch (static device globals — no allocation)
__device__ float g_buf[ROWS * Dd];      // g = h @ W           (1.6 MB)
__device__ float si_buf[ROWS * Hh];     // s_i
__device__ float sj_buf[ROWS * Hh];     // s_j
__device__ uint2 c3ph_g[512];           // packed tf32-hi B frags (ks*32+t4*8+g4)
__device__ uint2 c3pl_g[512];           // packed tf32-lo B frags
__device__ int   gate_ctr[2];           // [0]=c3 blocks done, [1]=gemm blocks done

__device__ __forceinline__ void cp_async16(uint32_t smem_addr, const void* gptr) {
    asm volatile("cp.async.cg.shared.global [%0], [%1], 16;\n"
                 :: "r"(smem_addr), "l"(gptr));
}
#define CP_COMMIT()  asm volatile("cp.async.commit_group;\n" ::: "memory")
#define CP_WAIT3()   asm volatile("cp.async.wait_group 3;\n" ::: "memory")

__device__ __forceinline__ uint32_t f2tf32(float x) {
    uint32_t r; asm("cvt.rna.tf32.f32 %0, %1;" : "=r"(r) : "f"(x)); return r;
}
__device__ __forceinline__ void ldm4(uint32_t& r0, uint32_t& r1, uint32_t& r2,
                                     uint32_t& r3, uint32_t addr) {
    asm volatile("ldmatrix.sync.aligned.m8n8.x4.shared.b16 {%0,%1,%2,%3}, [%4];"
                 : "=r"(r0), "=r"(r1), "=r"(r2), "=r"(r3) : "r"(addr));
}
__device__ __forceinline__ void mma_tf32(float& d0, float& d1, float& d2, float& d3,
                                         uint32_t a0, uint32_t a1, uint32_t a2,
                                         uint32_t a3, uint32_t b0, uint32_t b1) {
    asm volatile("mma.sync.aligned.m16n8k8.row.col.f32.tf32.tf32.f32 "
                 "{%0,%1,%2,%3}, {%4,%5,%6,%7}, {%8,%9}, {%0,%1,%2,%3};"
                 : "+f"(d0), "+f"(d1), "+f"(d2), "+f"(d3)
                 : "r"(a0), "r"(a1), "r"(a2), "r"(a3), "r"(b0), "r"(b1));
}

// ---------------------------------------------------------------------------
// ONE fused kernel.
//   blocks 0..199   : g = h @ W + fused s_i/s_j, then bump gate_ctr[1].
//   blocks 200..207 : c3 column + packed tf32 B frags, then bump gate_ctr[0].
//   blocks 208+     : attn row (bid-208). Ring fills start at cycle 0;
//                     spin on c3 gate (overlapped w/ fills); stage-1 raw s_e;
//                     spin on gemm gate; softmax w/ si+sj+mask fixup; stage 3.
// ---------------------------------------------------------------------------
__global__ void __launch_bounds__(256, 5)
fused_kernel(const float* __restrict__ h,   const float* __restrict__ W,
             const float* __restrict__ We,  const float* __restrict__ a,
             const float* __restrict__ dis, const int*   __restrict__ adj,
             float*       __restrict__ out)
{
    __shared__ __align__(16) float smem_pool[8 * 4 * 256];  // 32 KB rings / gemm hT
    __shared__ __align__(16) float esh2[208 * ES9];         // 7.5 KB logits [j][h]
    __shared__ __align__(16) float part[Hh * Dd];           // 4 KB stage-3 partials
    __shared__ float inv_sh[Hh];

    int tid = threadIdx.x;
    int bid = blockIdx.x;
    int lane = tid & 31;
    int warp = tid >> 5;

    if (bid < NGEMM) {
        // =================== producer paths ===================
        if (bid >= 200) {                // ---- c3 (one head per block)
            int hd = bid - 200;
            float* a3sh  = smem_pool;         // 16
            float* c3col = smem_pool + 16;    // 128
            if (tid < 16) a3sh[tid] = a[32 + tid];
            __syncthreads();
            if (tid < Dd) {
                const float4* row4 = (const float4*)(We + (size_t)tid * Dd + hd * 16);
                float s = 0.f;
                #pragma unroll
                for (int qv = 0; qv < 4; qv++) {
                    float4 w4 = row4[qv];
                    s += w4.x * a3sh[qv * 4 + 0] + w4.y * a3sh[qv * 4 + 1]
                       + w4.z * a3sh[qv * 4 + 2] + w4.w * a3sh[qv * 4 + 3];
                }
                c3col[tid] = s;
            }
            __syncthreads();
            if (tid < 64) {              // pack B fragments for this head
                int ks = tid >> 2, t4 = tid & 3;
                int kB = ks * 8 + t4;
                float v0 = c3col[kB], v1 = c3col[kB + 4];
                uint32_t h0 = f2tf32(v0), h1 = f2tf32(v1);
                int idx = ks * 32 + t4 * 8 + hd;
                c3ph_g[idx] = make_uint2(h0, h1);
                c3pl_g[idx] = make_uint2(f2tf32(v0 - __uint_as_float(h0)),
                                         f2tf32(v1 - __uint_as_float(h1)));
            }
            __threadfence();
            __syncthreads();
            if (tid == 0) atomicAdd(&gate_ctr[0], 1);
            return;
        }

        // ---- gemm: g = h @ W, fused s_i/s_j
        float* hT  = smem_pool;              // 128*20
        float* ash = smem_pool + Dd * HS;    // 48
        int row0 = bid * RPB;
        if (tid < 32) ash[tid] = a[tid];
        #pragma unroll 2
        for (int idx = tid; idx < RPB * Dd; idx += 256) {
            int r = idx >> 7, k = idx & 127;
            hT[k * HS + r] = h[(size_t)(row0 + r) * Dd + k];
        }
        __syncthreads();

        int cvec = tid & 31;
        int c0   = cvec * 4;
        int r0   = (tid >> 5) * 2;
        float acc0[4] = {0.f, 0.f, 0.f, 0.f};
        float acc1[4] = {0.f, 0.f, 0.f, 0.f};
        const float4* Wv = (const float4*)W;
        #pragma unroll 16
        for (int k = 0; k < Dd; k++) {
            float4 w4 = Wv[k * 32 + cvec];
            float2 h2 = *(const float2*)&hT[k * HS + r0];
            acc0[0] += h2.x * w4.x;  acc0[1] += h2.x * w4.y;
            acc0[2] += h2.x * w4.z;  acc0[3] += h2.x * w4.w;
            acc1[0] += h2.y * w4.x;  acc1[1] += h2.y * w4.y;
            acc1[2] += h2.y * w4.z;  acc1[3] += h2.y * w4.w;
        }
        *(float4*)&g_buf[(size_t)(row0 + r0)     * Dd + c0] =
            make_float4(acc0[0], acc0[1], acc0[2], acc0[3]);
        *(float4*)&g_buf[(size_t)(row0 + r0 + 1) * Dd + c0] =
            make_float4(acc1[0], acc1[1], acc1[2], acc1[3]);

        {   // fused s_i / s_j
            int head = c0 >> 4;
            int qb   = c0 & 15;
            const float* a1 = ash;
            const float* a2 = ash + 16;
            float pi0 = acc0[0]*a1[qb] + acc0[1]*a1[qb+1] + acc0[2]*a1[qb+2] + acc0[3]*a1[qb+3];
            float pj0 = acc0[0]*a2[qb] + acc0[1]*a2[qb+1] + acc0[2]*a2[qb+2] + acc0[3]*a2[qb+3];
            float pi1 = acc1[0]*a1[qb] + acc1[1]*a1[qb+1] + acc1[2]*a1[qb+2] + acc1[3]*a1[qb+3];
            float pj1 = acc1[0]*a2[qb] + acc1[1]*a2[qb+1] + acc1[2]*a2[qb+2] + acc1[3]*a2[qb+3];
            pi0 += __shfl_xor_sync(0xffffffffu, pi0, 1);
            pi0 += __shfl_xor_sync(0xffffffffu, pi0, 2);
            pj0 += __shfl_xor_sync(0xffffffffu, pj0, 1);
            pj0 += __shfl_xor_sync(0xffffffffu, pj0, 2);
            pi1 += __shfl_xor_sync(0xffffffffu, pi1, 1);
            pi1 += __shfl_xor_sync(0xffffffffu, pi1, 2);
            pj1 += __shfl_xor_sync(0xffffffffu, pj1, 1);
            pj1 += __shfl_xor_sync(0xffffffffu, pj1, 2);
            if ((tid & 3) == 0) {
                si_buf[(row0 + r0)     * Hh + head] = pi0;
                sj_buf[(row0 + r0)     * Hh + head] = pj0;
                si_buf[(row0 + r0 + 1) * Hh + head] = pi1;
                sj_buf[(row0 + r0 + 1) * Hh + head] = pj1;
            }
        }
        __threadfence();
        __syncthreads();
        if (tid == 0) atomicAdd(&gate_ctr[1], 1);
        return;
    }

    // =================== attn path ===================
    int row = bid - NGEMM;               // b*200 + i
    int b   = row / Nn;
    size_t rb = (size_t)row * Nn;
    int gbase = b * Nn;

    float* bufs = smem_pool;
    uint32_t buf_wa = (uint32_t)__cvta_generic_to_shared(bufs) + warp * 4096;
    int g4 = lane >> 2;
    int t4 = lane & 3;
    int laneoff = t4 * 8 + g4;
    int h0 = 2 * t4, h1 = h0 + 1;

    // Fill geometry: pass p covers rows p*8 + (lane>>2), unit u = lane&3.
    int u = lane & 3;
    uint32_t soff[2];
    uint32_t roffL[2][2];
    #pragma unroll
    for (int p = 0; p < 2; p++) {
        int r = p * 8 + (lane >> 2);
        soff[p] = (uint32_t)((r * 4 + (u ^ ((r >> 1) & 3))) * 16);
        #pragma unroll
        for (int ci = 0; ci < 2; ci++) {
            int j = (warp + ci * 8) * 16 + r;
            if (j > 199) j = 199;
            roffL[ci][p] = (uint32_t)(rb + j) * (Dd * 4) + (uint32_t)u * 16;
        }
    }
    int mi = lane >> 3, ri = lane & 7;
    int rr = ri + 8 * (mi & 1);
    int mh = mi >> 1;
    uint32_t ldoff[2];
    #pragma unroll
    for (int s = 0; s < 2; s++)
        ldoff[s] = (uint32_t)((rr * 4 + ((2 * s + mh) ^ ((rr >> 1) & 3))) * 16);

    // ---- Stage 1: dis @ c3 (raw s_e). Fills first, THEN c3 gate (overlapped).
    {
        int nc = (warp < 5) ? 2 : 1;
        int T  = nc * 8;

        auto issue = [&](int ti) {
            int ci = ti >> 3, kb = ti & 7;
            uint32_t sb = buf_wa + (uint32_t)(ti & 3) * 1024;
            const char* dbase = (const char*)dis + (kb << 6);
            cp_async16(sb + soff[0], dbase + roffL[ci][0]);
            cp_async16(sb + soff[1], dbase + roffL[ci][1]);
        };

        issue(0); CP_COMMIT();
        issue(1); CP_COMMIT();
        issue(2); CP_COMMIT();

        // c3 gate — overlapped with the 3 in-flight fills.
        if (tid == 0) {
            while (((volatile int*)gate_ctr)[0] != 8) __nanosleep(64);
            __threadfence();
        }
        __syncthreads();

        float d0 = 0.f, d1 = 0.f, d2 = 0.f, d3 = 0.f;
        for (int ti = 0; ti < T; ti++) {
            if (ti + 3 < T) issue(ti + 3);
            CP_COMMIT();
            CP_WAIT3();
            __syncwarp();

            uint32_t abase = buf_wa + (uint32_t)(ti & 3) * 1024;
            int kb = ti & 7;
            #pragma unroll
            for (int s = 0; s < 2; s++) {
                uint32_t a0, a1, a2, a3;
                ldm4(a0, a1, a2, a3, abase + ldoff[s]);

                float f0 = __uint_as_float(a0), f1 = __uint_as_float(a1);
                float f2 = __uint_as_float(a2), f3 = __uint_as_float(a3);
                uint32_t ah0 = f2tf32(f0), ah1 = f2tf32(f1);
                uint32_t ah2 = f2tf32(f2), ah3 = f2tf32(f3);
                uint32_t al0 = __float_as_uint(f0 - __uint_as_float(ah0));
                uint32_t al1 = __float_as_uint(f1 - __uint_as_float(ah1));
                uint32_t al2 = __float_as_uint(f2 - __uint_as_float(ah2));
                uint32_t al3 = __float_as_uint(f3 - __uint_as_float(ah3));

                int ks = kb * 2 + s;
                uint2 bh = __ldg(&c3ph_g[ks * 32 + laneoff]);
                uint2 bl = __ldg(&c3pl_g[ks * 32 + laneoff]);

                mma_tf32(d0, d1, d2, d3, ah0, ah1, ah2, ah3, bh.x, bh.y);
                mma_tf32(d0, d1, d2, d3, al0, al1, al2, al3, bh.x, bh.y);
                mma_tf32(d0, d1, d2, d3, ah0, ah1, ah2, ah3, bl.x, bl.y);
            }

            if (kb == 7) {   // store RAW s_e (fixup happens post-gate)
                int j0 = (warp + (ti >> 3) * 8) * 16;
                int jA = j0 + g4;
                if (jA < 200) { esh2[jA * ES9 + h0] = d0; esh2[jA * ES9 + h1] = d1; }
                int jB = j0 + 8 + g4;
                if (jB < 200) { esh2[jB * ES9 + h0] = d2; esh2[jB * ES9 + h1] = d3; }
                d0 = d1 = d2 = d3 = 0.f;
            }
        }
    }
    __syncthreads();

    // ---- gemm gate: si/sj/g must be ready.
    if (tid == 0) {
        while (((volatile int*)gate_ctr)[1] != 200) __nanosleep(64);
        __threadfence();
    }
    __syncthreads();

    // ---- Stage 2: softmax over j w/ fixup (si + sj + leaky + mask) in max pass.
    {
        int hh = warp;
        float sih = si_buf[row * Hh + hh];
        float m = -INFINITY;
        for (int j = lane; j < Nn; j += 32) {
            float e = esh2[j * ES9 + hh] + sih + sj_buf[(gbase + j) * Hh + hh];
            e = (e > 0.f) ? e : NEG_SLOPE * e;
            if (__ldg(&adj[rb + j]) == 0) e = -INFINITY;
            esh2[j * ES9 + hh] = e;
            m = fmaxf(m, e);
        }
        #pragma unroll
        for (int o = 16; o > 0; o >>= 1)
            m = fmaxf(m, __shfl_xor_sync(0xffffffffu, m, o));
        float s = 0.f;
        for (int j = lane; j < Nn; j += 32) {
            float p = __expf(esh2[j * ES9 + hh] - m);
            esh2[j * ES9 + hh] = p;
            s += p;
        }
        #pragma unroll
        for (int o = 16; o > 0; o >>= 1)
            s += __shfl_xor_sync(0xffffffffu, s, o);
        if (lane == 0) inv_sh[hh] = 1.f / s;
    }
    __syncthreads();

    // ---- Stage 3: out[d] = (1/s) * sum_j p[j][h(d)] * g[b,j,d]. Direct LDG.
    {
        const float4* gvec = (const float4*)g_buf;
        size_t gb = (size_t)b * Nn;
        int myh = lane >> 2;
        float ax = 0.f, ay = 0.f, az = 0.f, aw = 0.f;
        #pragma unroll 1
        for (int c = 0; c < 4; c++) {
            float4 gv[6]; float p[6];
            #pragma unroll
            for (int uu2 = 0; uu2 < 6; uu2++) {
                int jj = warp + 8 * (c * 6 + uu2);
                gv[uu2] = gvec[(gb + jj) * 32 + lane];
                p[uu2]  = esh2[jj * ES9 + myh];
            }
            #pragma unroll
            for (int uu2 = 0; uu2 < 6; uu2++) {
                ax += p[uu2] * gv[uu2].x;  ay += p[uu2] * gv[uu2].y;
                az += p[uu2] * gv[uu2].z;  aw += p[uu2] * gv[uu2].w;
            }
        }
        {
            int jj = warp + 192;
            float4 gv = gvec[(gb + jj) * 32 + lane];
            float  p  = esh2[jj * ES9 + myh];
            ax += p * gv.x;  ay += p * gv.y;  az += p * gv.z;  aw += p * gv.w;
        }
        *(float4*)&part[warp * Dd + lane * 4] = make_float4(ax, ay, az, aw);
        __syncthreads();
        if (tid < Dd) {
            int d = tid;
            float s = 0.f;
            #pragma unroll
            for (int w = 0; w < Hh; w++) s += part[w * Dd + d];
            out[(size_t)row * Dd + d] = s * inv_sh[d >> 4];
        }
    }
}

// ---------------------------------------------------------------------------
extern "C" void kernel_launch(void* const* d_in, const int* in_sizes, int n_in,
                              void* d_out, int out_size)
{
    const float* h   = (const float*)d_in[0];
    const int*   adj = (const int*)  d_in[1];
    const float* dis = (const float*)d_in[2];
    const float* W   = (const float*)d_in[3];
    const float* We  = (const float*)d_in[4];
    const float* a   = (const float*)d_in[5];
    float* out = (float*)d_out;

    void* ctr_addr = nullptr;
    cudaGetSymbolAddress(&ctr_addr, gate_ctr);
    cudaMemsetAsync(ctr_addr, 0, 2 * sizeof(int));   // reset gates (captured node)

    fused_kernel<<<NGEMM + ROWS, 256>>>(h, W, We, a, dis, adj, out);
}

// round 15
// speedup vs baseline: 1.0761x; 1.0761x over previous
#include <cuda_runtime.h>
#include <math.h>
#include <stdint.h>

#define Bb 16
#define Nn 200
#define Dd 128
#define Hh 8
#define ROWS (Bb*Nn)          // 3200
#define NEG_SLOPE 0.2f
#define RPB 16                // rows per gemm block
#define HS 20                 // hT row stride (floats)
#define ES9 9                 // esh2 row stride (conflict-free softmax)

// attn dynamic smem layout (floats) — R10 layout
#define SM_BUFS   0                       // 8 warps x 2 slots x 512 = 8192
#define SM_ESH    8192                    // 208*9 = 1872
#define SM_SJ     (SM_ESH + 1872)         // 1600
#define SM_C3HI   (SM_SJ + 1600)          // 1024
#define SM_C3LO   (SM_C3HI + 1024)        // 1024
#define SM_ADJ    (SM_C3LO + 1024)        // 200
#define SM_SI     (SM_ADJ + 200)          // 8
#define SM_INV    (SM_SI + 8)             // 8
#define SM_TOTALF (SM_INV + 8)            // 13928 floats = 55712 B

// Scratch (static device globals — no allocation)
__device__ float g_buf[ROWS * Dd];      // g = h @ W           (1.6 MB)
__device__ float si_buf[ROWS * Hh];     // s_i
__device__ float sj_buf[ROWS * Hh];     // s_j
__device__ float c3g[Dd * Hh];          // W_e folded with a3   [d][h]

__device__ __forceinline__ void cp_async16(uint32_t smem_addr, const void* gptr) {
    asm volatile("cp.async.cg.shared.global [%0], [%1], 16;\n"
                 :: "r"(smem_addr), "l"(gptr));
}
#define CP_COMMIT()  asm volatile("cp.async.commit_group;\n" ::: "memory")
#define CP_WAIT1()   asm volatile("cp.async.wait_group 1;\n" ::: "memory")

__device__ __forceinline__ uint32_t f2tf32(float x) {
    uint32_t r; asm("cvt.rna.tf32.f32 %0, %1;" : "=r"(r) : "f"(x)); return r;
}
__device__ __forceinline__ void ldm4(uint32_t& r0, uint32_t& r1, uint32_t& r2,
                                     uint32_t& r3, uint32_t addr) {
    asm volatile("ldmatrix.sync.aligned.m8n8.x4.shared.b16 {%0,%1,%2,%3}, [%4];"
                 : "=r"(r0), "=r"(r1), "=r"(r2), "=r"(r3) : "r"(addr));
}
__device__ __forceinline__ void mma_tf32(float& d0, float& d1, float& d2, float& d3,
                                         uint32_t a0, uint32_t a1, uint32_t a2,
                                         uint32_t a3, uint32_t b0, uint32_t b1) {
    asm volatile("mma.sync.aligned.m16n8k8.row.col.f32.tf32.tf32.f32 "
                 "{%0,%1,%2,%3}, {%4,%5,%6,%7}, {%8,%9}, {%0,%1,%2,%3};"
                 : "+f"(d0), "+f"(d1), "+f"(d2), "+f"(d3)
                 : "r"(a0), "r"(a1), "r"(a2), "r"(a3), "r"(b0), "r"(b1));
}

// ---------------------------------------------------------------------------
// Kernel A (R11 version, unroll 16): blocks 0..199: g = h @ W, s_i/s_j fused.
//           blocks 200..207: c3[d][h] = sum_q W_e[d,h*16+q]*a3[q].
// ---------------------------------------------------------------------------
__global__ void __launch_bounds__(256) gemm_fused(const float* __restrict__ h,
                                                  const float* __restrict__ W,
                                                  const float* __restrict__ We,
                                                  const float* __restrict__ a)
{
    __shared__ float hT[Dd * HS];
    __shared__ float ash[48];

    int t = threadIdx.x;

    if (blockIdx.x >= 200) {             // ---- c3 path (one head per block)
        int hd = blockIdx.x - 200;
        __shared__ float a3sh[16];
        if (t < 16) a3sh[t] = a[32 + t];
        __syncthreads();
        if (t < Dd) {
            const float4* row = (const float4*)(We + (size_t)t * Dd + hd * 16);
            float s = 0.f;
            #pragma unroll
            for (int qv = 0; qv < 4; qv++) {
                float4 w4 = row[qv];
                s += w4.x * a3sh[qv * 4 + 0] + w4.y * a3sh[qv * 4 + 1]
                   + w4.z * a3sh[qv * 4 + 2] + w4.w * a3sh[qv * 4 + 3];
            }
            c3g[t * Hh + hd] = s;
        }
        return;
    }

    int row0 = blockIdx.x * RPB;
    if (t < 32) ash[t] = a[t];

    #pragma unroll 2
    for (int idx = t; idx < RPB * Dd; idx += 256) {
        int r = idx >> 7, k = idx & 127;
        hT[k * HS + r] = h[(size_t)(row0 + r) * Dd + k];
    }
    __syncthreads();

    int cvec = t & 31;
    int c0   = cvec * 4;
    int r0   = (t >> 5) * 2;
    float acc0[4] = {0.f, 0.f, 0.f, 0.f};
    float acc1[4] = {0.f, 0.f, 0.f, 0.f};

    const float4* Wv = (const float4*)W;
    #pragma unroll 16
    for (int k = 0; k < Dd; k++) {
        float4 w4 = Wv[k * 32 + cvec];
        float2 h2 = *(const float2*)&hT[k * HS + r0];
        acc0[0] += h2.x * w4.x;  acc0[1] += h2.x * w4.y;
        acc0[2] += h2.x * w4.z;  acc0[3] += h2.x * w4.w;
        acc1[0] += h2.y * w4.x;  acc1[1] += h2.y * w4.y;
        acc1[2] += h2.y * w4.z;  acc1[3] += h2.y * w4.w;
    }
    *(float4*)&g_buf[(size_t)(row0 + r0)     * Dd + c0] =
        make_float4(acc0[0], acc0[1], acc0[2], acc0[3]);
    *(float4*)&g_buf[(size_t)(row0 + r0 + 1) * Dd + c0] =
        make_float4(acc1[0], acc1[1], acc1[2], acc1[3]);

    {   // fused s_i / s_j
        int head = c0 >> 4;
        int qb   = c0 & 15;
        const float* a1 = ash;
        const float* a2 = ash + 16;
        float pi0 = acc0[0]*a1[qb] + acc0[1]*a1[qb+1] + acc0[2]*a1[qb+2] + acc0[3]*a1[qb+3];
        float pj0 = acc0[0]*a2[qb] + acc0[1]*a2[qb+1] + acc0[2]*a2[qb+2] + acc0[3]*a2[qb+3];
        float pi1 = acc1[0]*a1[qb] + acc1[1]*a1[qb+1] + acc1[2]*a1[qb+2] + acc1[3]*a1[qb+3];
        float pj1 = acc1[0]*a2[qb] + acc1[1]*a2[qb+1] + acc1[2]*a2[qb+2] + acc1[3]*a2[qb+3];
        pi0 += __shfl_xor_sync(0xffffffffu, pi0, 1);
        pi0 += __shfl_xor_sync(0xffffffffu, pi0, 2);
        pj0 += __shfl_xor_sync(0xffffffffu, pj0, 1);
        pj0 += __shfl_xor_sync(0xffffffffu, pj0, 2);
        pi1 += __shfl_xor_sync(0xffffffffu, pi1, 1);
        pi1 += __shfl_xor_sync(0xffffffffu, pi1, 2);
        pj1 += __shfl_xor_sync(0xffffffffu, pj1, 1);
        pj1 += __shfl_xor_sync(0xffffffffu, pj1, 2);
        if ((t & 3) == 0) {
            si_buf[(row0 + r0)     * Hh + head] = pi0;
            sj_buf[(row0 + r0)     * Hh + head] = pj0;
            si_buf[(row0 + r0 + 1) * Hh + head] = pi1;
            sj_buf[(row0 + r0 + 1) * Hh + head] = pj1;
        }
    }
}

// ---------------------------------------------------------------------------
// Kernel B (R10 version, byte-identical): per (b,i). Stage 1: tensor-core
// 3xTF32 with double-buffered 2KB cp.async tiles. Stage 2 softmax.
// Stage 3 direct-LDG attn @ g.
// ---------------------------------------------------------------------------
__global__ void __launch_bounds__(256, 4) attn_kernel(const float* __restrict__ dis,
                                                      const int*   __restrict__ adj,
                                                      float*       __restrict__ out)
{
    extern __shared__ __align__(16) float dsm[];
    float*    bufs   = dsm + SM_BUFS;
    float*    esh2   = dsm + SM_ESH;
    float*    sjsh   = dsm + SM_SJ;
    uint32_t* c3hi_s = (uint32_t*)(dsm + SM_C3HI);
    uint32_t* c3lo_s = (uint32_t*)(dsm + SM_C3LO);
    int*      adjsh  = (int*)(dsm + SM_ADJ);
    float*    si_sh  = dsm + SM_SI;
    float*    inv_sh = dsm + SM_INV;

    int tid  = threadIdx.x;
    int lane = tid & 31;
    int warp = tid >> 5;                 // 0..7
    int row  = blockIdx.x;               // b*200 + i
    int b    = row / Nn;
    size_t rb = (size_t)row * Nn;

    // Prologue loads
    for (int idx = tid; idx < Nn * Hh; idx += 256)
        sjsh[idx] = sj_buf[(size_t)b * Nn * Hh + idx];
    for (int idx = tid; idx < Nn; idx += 256)
        adjsh[idx] = adj[rb + idx];
    if (tid < Hh) si_sh[tid] = si_buf[row * Hh + tid];
    for (int idx = tid; idx < Dd * Hh; idx += 256) {
        float v = c3g[idx];
        uint32_t hi = f2tf32(v);
        c3hi_s[idx] = hi;
        c3lo_s[idx] = f2tf32(v - __uint_as_float(hi));
    }
    __syncthreads();

    // Per-warp double buffer: 2 slots x 2KB.
    uint32_t buf_sa = (uint32_t)__cvta_generic_to_shared(bufs) + warp * 4096;
    int g4 = lane >> 2;                  // groupID
    int t4 = lane & 3;                   // threadID-in-group

    // Lane-invariant fill geometry.
    int lr = lane >> 3;                  // 0..3
    int u  = lane & 7;                   // 0..7
    uint32_t soff[4];
    #pragma unroll
    for (int it = 0; it < 4; it++) {
        int r = it * 4 + lr;
        soff[it] = (uint32_t)((r * 8 + (u ^ (r & 7))) * 16);
    }
    // ldmatrix geometry (lane-invariant parts)
    int mi = lane >> 3, ri = lane & 7;
    int rr = ri + 8 * (mi & 1);
    int mh = mi >> 1;
    uint32_t rr8 = (uint32_t)(rr * 8);

    // ---- Stage 1: chunks of 16 j-rows; warp w owns chunks {w, w+8} (<13).
    {
        int nc = (warp < 5) ? 2 : 1;
        int T  = nc * 4;                 // tiles: ti = ci*4 + kb

        auto issue = [&](int ti, int slot) {
            int ci = ti >> 2, kb = ti & 3;
            int j0 = (warp + ci * 8) * 16;
            uint32_t sb = buf_sa + (uint32_t)slot * 2048;
            #pragma unroll
            for (int it = 0; it < 4; it++) {
                int j = j0 + it * 4 + lr;
                if (j > 199) j = 199;
                cp_async16(sb + soff[it],
                           dis + (rb + j) * (size_t)Dd + kb * 32 + u * 4);
            }
        };

        float d0 = 0.f, d1 = 0.f, d2 = 0.f, d3 = 0.f;
        issue(0, 0);
        CP_COMMIT();
        for (int ti = 0; ti < T; ti++) {
            if (ti + 1 < T) issue(ti + 1, (ti + 1) & 1);
            CP_COMMIT();
            CP_WAIT1();
            __syncwarp();

            uint32_t abase = buf_sa + (uint32_t)(ti & 1) * 2048;
            int kb = ti & 3;
            #pragma unroll
            for (int s = 0; s < 4; s++) {
                int uu = 2 * s + mh;
                uint32_t a0, a1, a2, a3;
                ldm4(a0, a1, a2, a3, abase + (rr8 + (uint32_t)(uu ^ ri)) * 16);

                uint32_t ah0 = f2tf32(__uint_as_float(a0));
                uint32_t ah1 = f2tf32(__uint_as_float(a1));
                uint32_t ah2 = f2tf32(__uint_as_float(a2));
                uint32_t ah3 = f2tf32(__uint_as_float(a3));
                uint32_t al0 = f2tf32(__uint_as_float(a0) - __uint_as_float(ah0));
                uint32_t al1 = f2tf32(__uint_as_float(a1) - __uint_as_float(ah1));
                uint32_t al2 = f2tf32(__uint_as_float(a2) - __uint_as_float(ah2));
                uint32_t al3 = f2tf32(__uint_as_float(a3) - __uint_as_float(ah3));

                int kB = kb * 32 + s * 8 + t4;
                uint32_t bh0 = c3hi_s[kB * Hh + g4];
                uint32_t bh1 = c3hi_s[(kB + 4) * Hh + g4];
                uint32_t bl0 = c3lo_s[kB * Hh + g4];
                uint32_t bl1 = c3lo_s[(kB + 4) * Hh + g4];

                mma_tf32(d0, d1, d2, d3, ah0, ah1, ah2, ah3, bh0, bh1);
                mma_tf32(d0, d1, d2, d3, al0, al1, al2, al3, bh0, bh1);
                mma_tf32(d0, d1, d2, d3, ah0, ah1, ah2, ah3, bl0, bl1);
            }

            if (kb == 3) {   // epilogue for chunk ci = ti>>2
                int j0 = (warp + (ti >> 2) * 8) * 16;
                int h0 = 2 * t4, h1 = h0 + 1;
                int jA = j0 + g4;
                if (jA < 200) {
                    float e0 = d0 + si_sh[h0] + sjsh[jA * Hh + h0];
                    float e1 = d1 + si_sh[h1] + sjsh[jA * Hh + h1];
                    e0 = (e0 > 0.f) ? e0 : NEG_SLOPE * e0;
                    e1 = (e1 > 0.f) ? e1 : NEG_SLOPE * e1;
                    if (adjsh[jA] == 0) { e0 = -INFINITY; e1 = -INFINITY; }
                    esh2[jA * ES9 + h0] = e0;
                    esh2[jA * ES9 + h1] = e1;
                }
                int jB = j0 + 8 + g4;
                if (jB < 200) {
                    float e2 = d2 + si_sh[h0] + sjsh[jB * Hh + h0];
                    float e3 = d3 + si_sh[h1] + sjsh[jB * Hh + h1];
                    e2 = (e2 > 0.f) ? e2 : NEG_SLOPE * e2;
                    e3 = (e3 > 0.f) ? e3 : NEG_SLOPE * e3;
                    if (adjsh[jB] == 0) { e2 = -INFINITY; e3 = -INFINITY; }
                    esh2[jB * ES9 + h0] = e2;
                    esh2[jB * ES9 + h1] = e3;
                }
                d0 = d1 = d2 = d3 = 0.f;
            }
        }
    }
    __syncthreads();

    // ---- Stage 2: softmax over j, one warp per head (stride-9: no conflicts).
    {
        int hh = warp;
        float m = -INFINITY;
        for (int j = lane; j < Nn; j += 32)
            m = fmaxf(m, esh2[j * ES9 + hh]);
        #pragma unroll
        for (int o = 16; o > 0; o >>= 1)
            m = fmaxf(m, __shfl_xor_sync(0xffffffffu, m, o));
        float s = 0.f;
        for (int j = lane; j < Nn; j += 32) {
            float p = __expf(esh2[j * ES9 + hh] - m);
            esh2[j * ES9 + hh] = p;
            s += p;
        }
        #pragma unroll
        for (int o = 16; o > 0; o >>= 1)
            s += __shfl_xor_sync(0xffffffffu, s, o);
        if (lane == 0) inv_sh[hh] = 1.f / s;
    }
    __syncthreads();

    // ---- Stage 3: out[d] = (1/s) * sum_j p[j][h(d)] * g[b,j,d]. Direct LDG.
    {
        const float4* gvec = (const float4*)g_buf;
        size_t gb = (size_t)b * Nn;
        int myh = lane >> 2;
        float ax = 0.f, ay = 0.f, az = 0.f, aw = 0.f;
        #pragma unroll 1
        for (int c = 0; c < 4; c++) {
            float4 gv[6]; float p[6];
            #pragma unroll
            for (int uu2 = 0; uu2 < 6; uu2++) {
                int jj = warp + 8 * (c * 6 + uu2);
                gv[uu2] = gvec[(gb + jj) * 32 + lane];
                p[uu2]  = esh2[jj * ES9 + myh];
            }
            #pragma unroll
            for (int uu2 = 0; uu2 < 6; uu2++) {
                ax += p[uu2] * gv[uu2].x;  ay += p[uu2] * gv[uu2].y;
                az += p[uu2] * gv[uu2].z;  aw += p[uu2] * gv[uu2].w;
            }
        }
        {
            int jj = warp + 192;
            float4 gv = gvec[(gb + jj) * 32 + lane];
            float  p  = esh2[jj * ES9 + myh];
            ax += p * gv.x;  ay += p * gv.y;  az += p * gv.z;  aw += p * gv.w;
        }
        float* part = sjsh;                     // alias (sjsh dead now)
        *(float4*)&part[warp * Dd + lane * 4] = make_float4(ax, ay, az, aw);
        __syncthreads();
        if (tid < Dd) {
            int d = tid;
            float s = 0.f;
            #pragma unroll
            for (int w = 0; w < Hh; w++) s += part[w * Dd + d];
            out[(size_t)row * Dd + d] = s * inv_sh[d >> 4];
        }
    }
}

// ---------------------------------------------------------------------------
extern "C" void kernel_launch(void* const* d_in, const int* in_sizes, int n_in,
                              void* d_out, int out_size)
{
    const float* h   = (const float*)d_in[0];
    const int*   adj = (const int*)  d_in[1];
    const float* dis = (const float*)d_in[2];
    const float* W   = (const float*)d_in[3];
    const float* We  = (const float*)d_in[4];
    const float* a   = (const float*)d_in[5];
    float* out = (float*)d_out;

    size_t smem = SM_TOTALF * sizeof(float);   // 55712 B
    cudaFuncSetAttribute(attn_kernel, cudaFuncAttributeMaxDynamicSharedMemorySize,
                         (int)smem);

    gemm_fused<<<208, 256>>>(h, W, We, a);
    attn_kernel<<<ROWS, 256, smem>>>(dis, adj, out);
}